// round 7
// baseline (speedup 1.0000x reference)
#include <cuda_runtime.h>
#include <cuda_bf16.h>
#include <cstdint>

// ---------------- problem constants ----------------
constexpr int N_USERS  = 29858;
constexpr int N_ITEMS  = 40981;
constexpr int N_TOT    = 70839;
constexpr int D        = 64;
constexpr int F        = 512;
constexpr int N_LAYERS = 3;
constexpr int NPAD     = 70912;                 // 554 * 128
constexpr int NU_ELEMS = N_USERS * D;
constexpr int NTOT4    = N_TOT * D / 4;

constexpr int KC           = 32;                // K per pipeline chunk
constexpr int CH_TOT       = NPAD / KC;         // 2216
constexpr int KSPLITS      = 74;                // GEMM1 split-K (grid 296)
constexpr int CH_PER_SPLIT = (CH_TOT + KSPLITS - 1) / KSPLITS;  // 30

// smem stage: Ah 8K | Al 8K | Bh 4K | Bl 4K = 24 KB; 4 slots = 96 KB
constexpr int A_OFF_L = 8192;
constexpr int B_OFF_H = 16384;
constexpr int B_OFF_L = 20480;
constexpr int STAGE   = 24576;
constexpr int GEMM_SMEM = 4 * STAGE + 1024;

// ---------------- scratch (static device globals; no allocation) -------------
__device__ __align__(128) float          g_acc[N_TOT * D];
__device__ __align__(128) unsigned short g_eh[(size_t)NPAD * D];   // ego hi [n][64]
__device__ __align__(128) unsigned short g_el[(size_t)NPAD * D];   // ego lo
__device__ __align__(128) unsigned short g_wh[D * F];              // W^T hi [64][512]
__device__ __align__(128) unsigned short g_wl[D * F];              // W^T lo
__device__ __align__(128) float          g_p1[KSPLITS * 4 * 128 * D];

// ---------------- helpers ----------------
__device__ __forceinline__ uint32_t smem_u32(const void* p) {
    uint32_t a;
    asm("{ .reg .u64 t; cvta.to.shared.u64 t, %1; cvt.u32.u64 %0, t; }"
        : "=r"(a) : "l"(p));
    return a;
}
__device__ __forceinline__ uint32_t swz(uint32_t o) { return o ^ ((o >> 3) & 0x70); }

__device__ __forceinline__ void cp16(uint32_t dst, const void* src) {
    asm volatile("cp.async.cg.shared.global [%0], [%1], 16;"
                 :: "r"(dst), "l"(src) : "memory");
}
__device__ __forceinline__ void cp_commit() {
    asm volatile("cp.async.commit_group;" ::: "memory");
}
template <int N>
__device__ __forceinline__ void cp_wait() {
    asm volatile("cp.async.wait_group %0;" :: "n"(N) : "memory");
}

__device__ __forceinline__ void split8(const float* f, uint4& hi, uint4& lo) {
    unsigned int hw[4], lw[4];
#pragma unroll
    for (int i = 0; i < 4; i++) {
        __nv_bfloat16 h0 = __float2bfloat16(f[2 * i]);
        __nv_bfloat16 h1 = __float2bfloat16(f[2 * i + 1]);
        float r0 = f[2 * i]     - __bfloat162float(h0);
        float r1 = f[2 * i + 1] - __bfloat162float(h1);
        __nv_bfloat16 l0 = __float2bfloat16(r0);
        __nv_bfloat16 l1 = __float2bfloat16(r1);
        hw[i] = (unsigned)__bfloat16_as_ushort(h0) | ((unsigned)__bfloat16_as_ushort(h1) << 16);
        lw[i] = (unsigned)__bfloat16_as_ushort(l0) | ((unsigned)__bfloat16_as_ushort(l1) << 16);
    }
    hi = make_uint4(hw[0], hw[1], hw[2], hw[3]);
    lo = make_uint4(lw[0], lw[1], lw[2], lw[3]);
}

__device__ __forceinline__ void ldsm_x4(uint32_t* r, uint32_t a) {
    asm volatile("ldmatrix.sync.aligned.m8n8.x4.shared.b16 {%0,%1,%2,%3}, [%4];"
                 : "=r"(r[0]), "=r"(r[1]), "=r"(r[2]), "=r"(r[3]) : "r"(a));
}
__device__ __forceinline__ void ldsm_x4_t(uint32_t* r, uint32_t a) {
    asm volatile("ldmatrix.sync.aligned.m8n8.x4.trans.shared.b16 {%0,%1,%2,%3}, [%4];"
                 : "=r"(r[0]), "=r"(r[1]), "=r"(r[2]), "=r"(r[3]) : "r"(a));
}
__device__ __forceinline__ void mma_bf16(float* c, const uint32_t* a,
                                         uint32_t b0, uint32_t b1) {
    asm volatile(
        "mma.sync.aligned.m16n8k16.row.col.f32.bf16.bf16.f32 "
        "{%0,%1,%2,%3}, {%4,%5,%6,%7}, {%8,%9}, {%0,%1,%2,%3};"
        : "+f"(c[0]), "+f"(c[1]), "+f"(c[2]), "+f"(c[3])
        : "r"(a[0]), "r"(a[1]), "r"(a[2]), "r"(a[3]), "r"(b0), "r"(b1));
}

// ---------------- K0: acc = concat(user,item); ego hi/lo split ---------------
__global__ void k_init(const float* __restrict__ u, const float* __restrict__ it) {
    int i = blockIdx.x * blockDim.x + threadIdx.x;
    if (i < (NPAD - N_TOT) * D / 4) {
        uint2 z = make_uint2(0u, 0u);
        *(uint2*)(g_eh + (size_t)N_TOT * D + i * 4) = z;
        *(uint2*)(g_el + (size_t)N_TOT * D + i * 4) = z;
    }
    if (i >= NTOT4) return;
    int e = i << 2;
    float4 t;
    if (e < NU_ELEMS) t = *(const float4*)(u + e);
    else              t = *(const float4*)(it + (e - NU_ELEMS));
    *(float4*)(g_acc + e) = t;
    float vals[4] = {t.x, t.y, t.z, t.w};
    unsigned int hw[2], lw[2];
#pragma unroll
    for (int p = 0; p < 2; p++) {
        __nv_bfloat16 h0 = __float2bfloat16(vals[2 * p]);
        __nv_bfloat16 h1 = __float2bfloat16(vals[2 * p + 1]);
        float r0 = vals[2 * p]     - __bfloat162float(h0);
        float r1 = vals[2 * p + 1] - __bfloat162float(h1);
        hw[p] = (unsigned)__bfloat16_as_ushort(h0) |
                ((unsigned)__bfloat16_as_ushort(h1) << 16);
        lw[p] = (unsigned)__bfloat16_as_ushort(__float2bfloat16(r0)) |
                ((unsigned)__bfloat16_as_ushort(__float2bfloat16(r1)) << 16);
    }
    *(uint2*)(g_eh + e) = make_uint2(hw[0], hw[1]);
    *(uint2*)(g_el + e) = make_uint2(lw[0], lw[1]);
}

// ---------------- reduce partials, fold filters, split W^T ----------------
// 4 threads per output element, shfl combine. grid 512 x 256.
__global__ void k_reduce1(const float* __restrict__ filt) {
    int gid = blockIdx.x * blockDim.x + threadIdx.x;  // 0..131071
    int out = gid >> 2, sub = gid & 3;
    int f = out >> 6, d = out & 63;
    int mt = f >> 7, fl = f & 127;
    float s = 0.f;
#pragma unroll 4
    for (int ks = sub; ks < KSPLITS; ks += 4)
        s += g_p1[((ks << 2) + mt) * 8192 + fl * 64 + d];
    s += __shfl_down_sync(0xffffffffu, s, 1);
    s += __shfl_down_sync(0xffffffffu, s, 2);
    if (sub == 0) {
        s *= filt[f];
        __nv_bfloat16 h = __float2bfloat16(s);
        float r = s - __bfloat162float(h);
        g_wh[d * F + f] = __bfloat16_as_ushort(h);
        g_wl[d * F + f] = __bfloat16_as_ushort(__float2bfloat16(r));
    }
}

// ---------------- pipelined warp-MMA GEMM ----------------
// C[128 x 64] = A[128 x K] * B[64 x K]^T, hi/lo bf16 split (3 MMA terms)
// MODE 0 (proj = V^T ego):  A = fp32 V slice [KC n][128 f] (converted), B = ego hi/lo
// MODE 1 (ego' = V W):      A = fp32 V rows  [128 m][KC f] (converted), B = W^T hi/lo
template <int MODE>
__global__ __launch_bounds__(256, 2) void k_gemm(const float* __restrict__ vsrc) {
    extern __shared__ char smraw[];
    const uint32_t smb = smem_u32(smraw);
    const uint32_t sm0 = (smb + 1023) & ~1023u;
    char* smp = smraw + (sm0 - smb);

    const int tid  = threadIdx.x;
    const int w    = tid >> 5;
    const int lane = tid & 31;

    int m0, c0, nc;
    if (MODE == 0) {
        int mt = blockIdx.x & 3;
        int ks = blockIdx.x >> 2;
        m0 = mt * 128;                         // f-tile origin
        c0 = ks * CH_PER_SPLIT;
        nc = min(CH_PER_SPLIT, CH_TOT - c0);
    } else {
        m0 = blockIdx.x * 128;                 // n-tile origin
        c0 = 0;
        nc = F / KC;                           // 16
    }

    float acc[8][4];
#pragma unroll
    for (int nt = 0; nt < 8; nt++)
#pragma unroll
        for (int j = 0; j < 4; j++) acc[nt][j] = 0.f;

    // ---- A LDG (fp32, guarded) into register bank ----
    auto ldgA = [&](int ch, float* ar) {
        if (ch >= nc) return;
        const int k0 = (c0 + ch) * KC;
#pragma unroll
        for (int r = 0; r < 2; r++) {
            int j = tid + r * 256;
            const float* src;
            bool ok;
            if (MODE == 0) {
                int n = j >> 4, seg = (j >> 3) & 1, q = j & 7;
                int gn = k0 + n;
                ok = gn < N_TOT;
                src = vsrc + (size_t)gn * F + m0 + seg * 64 + q * 8;
            } else {
                int m = j >> 2, q = j & 3;
                int gm = m0 + m;
                ok = gm < N_TOT;
                src = vsrc + (size_t)gm * F + k0 + q * 8;
            }
            float4 x0 = make_float4(0.f, 0.f, 0.f, 0.f), x1 = x0;
            if (ok) { x0 = *(const float4*)src; x1 = *(const float4*)(src + 4); }
            ar[r * 8 + 0] = x0.x; ar[r * 8 + 1] = x0.y;
            ar[r * 8 + 2] = x0.z; ar[r * 8 + 3] = x0.w;
            ar[r * 8 + 4] = x1.x; ar[r * 8 + 5] = x1.y;
            ar[r * 8 + 6] = x1.z; ar[r * 8 + 7] = x1.w;
        }
    };
    // ---- A split + STS ----
    auto stsA = [&](int ch, const float* ar) {
        if (ch >= nc) return;
        char* sb = smp + (ch & 3) * STAGE;
#pragma unroll
        for (int r = 0; r < 2; r++) {
            uint4 hi, lo;
            split8(ar + r * 8, hi, lo);
            int j = tid + r * 256;
            uint32_t d;
            if (MODE == 0) {
                int n = j >> 4, seg = (j >> 3) & 1, q = j & 7;
                d = seg * 4096 + swz(n * 128 + q * 16);
            } else {
                int m = j >> 2, q = j & 3;
                d = swz(m * 64 + q * 16);
            }
            *(uint4*)(sb + d)           = hi;
            *(uint4*)(sb + A_OFF_L + d) = lo;
        }
    };
    // ---- B cp.async (bf16 pairs, pure copy) ----
    auto cpB = [&](int ch) {
        if (ch < nc) {
            const int k0 = (c0 + ch) * KC;
            uint32_t sbuf = sm0 + (uint32_t)(ch & 3) * STAGE;
            if (MODE == 0) {
                int n = tid >> 3, q = tid & 7;
                size_t src = (size_t)(k0 + n) * D + q * 8;
                uint32_t d = swz(n * 128 + q * 16);
                cp16(sbuf + B_OFF_H + d, g_eh + src);
                cp16(sbuf + B_OFF_L + d, g_el + src);
            } else {
                int dd = tid >> 2, q = tid & 3;
                size_t src = (size_t)dd * F + k0 + q * 8;
                uint32_t d = swz(dd * 64 + q * 16);
                cp16(sbuf + B_OFF_H + d, g_wh + src);
                cp16(sbuf + B_OFF_L + d, g_wl + src);
            }
        }
        cp_commit();
    };

    // fragment addressing
    const int a_k   = (lane & 7) | ((lane & 16) >> 1);        // MODE 0 (trans A)
    const uint32_t a_seg = (uint32_t)(w >> 2) * 4096;
    const uint32_t a_f2  = (uint32_t)((w * 16 + (lane & 8)) & 63) * 2;
    const int bt_k  = lane & 15;                              // MODE 0 (trans B)
    const int bt_n8 = ((lane >> 4) & 1) * 8;
    const int a_row  = w * 16 + (lane & 15);                  // MODE 1 (plain A)
    const int a_colh = (lane >> 4) * 8;
    const int bp_row = lane & 15;                             // MODE 1 (plain B)
    const int bp_k8  = ((lane >> 4) & 1) * 8;

    auto compute = [&](int ch) {
        const uint32_t buf = sm0 + (uint32_t)(ch & 3) * STAGE;
        const uint32_t sAh = buf, sAl = buf + A_OFF_L;
        const uint32_t sBh = buf + B_OFF_H, sBl = buf + B_OFF_L;
#pragma unroll
        for (int ks = 0; ks < KC / 16; ks++) {
            uint32_t ah[4], al[4];
            if (MODE == 0) {
                uint32_t ao = a_seg + swz((uint32_t)((ks * 16 + a_k) * 128) + a_f2);
                ldsm_x4_t(ah, sAh + ao);
                ldsm_x4_t(al, sAl + ao);
            } else {
                uint32_t ao = swz((uint32_t)(a_row * 64 + (ks * 16 + a_colh) * 2));
                ldsm_x4(ah, sAh + ao);
                ldsm_x4(al, sAl + ao);
            }
#pragma unroll
            for (int nt2 = 0; nt2 < 4; nt2++) {
                uint32_t bh[4], bl[4];
                if (MODE == 0) {
                    uint32_t bo = swz((uint32_t)((ks * 16 + bt_k) * 128 +
                                                 (nt2 * 16 + bt_n8) * 2));
                    ldsm_x4_t(bh, sBh + bo);
                    ldsm_x4_t(bl, sBl + bo);
                    float* cE = acc[2 * nt2];
                    float* cO = acc[2 * nt2 + 1];
                    mma_bf16(cE, ah, bh[0], bh[1]);
                    mma_bf16(cE, ah, bl[0], bl[1]);
                    mma_bf16(cE, al, bh[0], bh[1]);
                    mma_bf16(cO, ah, bh[2], bh[3]);
                    mma_bf16(cO, ah, bl[2], bl[3]);
                    mma_bf16(cO, al, bh[2], bh[3]);
                } else {
                    uint32_t bo = swz((uint32_t)((nt2 * 16 + bp_row) * 64 +
                                                 (ks * 16 + bp_k8) * 2));
                    ldsm_x4(bh, sBh + bo);
                    ldsm_x4(bl, sBl + bo);
                    float* cE = acc[2 * nt2];
                    float* cO = acc[2 * nt2 + 1];
                    mma_bf16(cE, ah, bh[0], bh[2]);
                    mma_bf16(cE, ah, bl[0], bl[2]);
                    mma_bf16(cE, al, bh[0], bh[2]);
                    mma_bf16(cO, ah, bh[1], bh[3]);
                    mma_bf16(cO, ah, bl[1], bl[3]);
                    mma_bf16(cO, al, bh[1], bh[3]);
                }
            }
        }
    };

    // ---- software pipeline: A via 2-bank LDG prefetch, B via cp.async 2-ahead
    float aA[16], aB[16];
    ldgA(0, aA);
    ldgA(1, aB);
    cpB(0);
    cpB(1);
    stsA(0, aA);

    int ch = 0;
    while (ch < nc) {
        // even sub-iter (A(ch+1) in aB, LDG next into aA)
        cpB(ch + 2);
        cp_wait<2>();
        __syncthreads();
        compute(ch);
        stsA(ch + 1, aB);
        ldgA(ch + 2, aA);
        ch++;
        if (ch >= nc) break;
        // odd sub-iter (A(ch+1) in aA, LDG next into aB)
        cpB(ch + 2);
        cp_wait<2>();
        __syncthreads();
        compute(ch);
        stsA(ch + 1, aA);
        ldgA(ch + 2, aB);
        ch++;
    }

    // ---- epilogue ----
    const int r0   = w * 16 + (lane >> 2);
    const int ncol = 2 * (lane & 3);
    if (MODE == 0) {
        float* out = g_p1 + (size_t)blockIdx.x * 8192;
#pragma unroll
        for (int nt = 0; nt < 8; nt++) {
            int n = nt * 8 + ncol;
            *(float2*)(out + r0 * 64 + n)       = make_float2(acc[nt][0], acc[nt][1]);
            *(float2*)(out + (r0 + 8) * 64 + n) = make_float2(acc[nt][2], acc[nt][3]);
        }
    } else {
#pragma unroll
        for (int half = 0; half < 2; half++) {
            int m = m0 + r0 + half * 8;
            if (m >= N_TOT) continue;
            float* ap = g_acc + (size_t)m * D;
            unsigned short* ehp = g_eh + (size_t)m * D;
            unsigned short* elp = g_el + (size_t)m * D;
#pragma unroll
            for (int nt = 0; nt < 8; nt++) {
                int n = nt * 8 + ncol;
                float cx = acc[nt][half * 2], cy = acc[nt][half * 2 + 1];
                float2 a = *(float2*)(ap + n);
                a.x += cx; a.y += cy;
                *(float2*)(ap + n) = a;
                __nv_bfloat16 hx = __float2bfloat16(cx);
                __nv_bfloat16 hy = __float2bfloat16(cy);
                float rx = cx - __bfloat162float(hx);
                float ry = cy - __bfloat162float(hy);
                unsigned int hw = (unsigned)__bfloat16_as_ushort(hx) |
                                  ((unsigned)__bfloat16_as_ushort(hy) << 16);
                unsigned int lw = (unsigned)__bfloat16_as_ushort(__float2bfloat16(rx)) |
                                  ((unsigned)__bfloat16_as_ushort(__float2bfloat16(ry)) << 16);
                *(unsigned int*)(ehp + n) = hw;
                *(unsigned int*)(elp + n) = lw;
            }
        }
    }
}

// ---------------- K4: out = acc / (L+1) ----------------
__global__ void k_final(float* __restrict__ out) {
    int i = blockIdx.x * blockDim.x + threadIdx.x;
    if (i >= NTOT4) return;
    int e = i << 2;
    float4 t = *(const float4*)(g_acc + e);
    t.x *= 0.25f; t.y *= 0.25f; t.z *= 0.25f; t.w *= 0.25f;
    *(float4*)(out + e) = t;
}

// ---------------- launcher ----------------
extern "C" void kernel_launch(void* const* d_in, const int* in_sizes, int n_in,
                              void* d_out, int out_size) {
    const float* user    = (const float*)d_in[0];
    const float* item    = (const float*)d_in[1];
    const float* v       = (const float*)d_in[2];
    const float* filters = (const float*)d_in[3];
    float* out = (float*)d_out;

    cudaFuncSetAttribute(k_gemm<0>, cudaFuncAttributeMaxDynamicSharedMemorySize, GEMM_SMEM);
    cudaFuncSetAttribute(k_gemm<1>, cudaFuncAttributeMaxDynamicSharedMemorySize, GEMM_SMEM);

    const int ew_blocks = (NTOT4 + 255) / 256;
    k_init<<<ew_blocks, 256>>>(user, item);

    for (int l = 0; l < N_LAYERS; l++) {
        k_gemm<0><<<KSPLITS * 4, 256, GEMM_SMEM>>>(v);       // proj partials
        k_reduce1<<<512, 256>>>(filters + l * F);            // W^T hi/lo
        k_gemm<1><<<NPAD / 128, 256, GEMM_SMEM>>>(v);        // ego' = V W ; acc+=, split
    }

    k_final<<<ew_blocks, 256>>>(out);
}

// round 8
// speedup vs baseline: 1.0207x; 1.0207x over previous
#include <cuda_runtime.h>
#include <cuda_bf16.h>
#include <cstdint>

// ---------------- problem constants ----------------
constexpr int N_USERS  = 29858;
constexpr int N_ITEMS  = 40981;
constexpr int N_TOT    = 70839;
constexpr int D        = 64;
constexpr int F        = 512;
constexpr int N_LAYERS = 3;
constexpr int NPAD     = 70912;                 // 554 * 128
constexpr int NU_ELEMS = N_USERS * D;
constexpr int NTOT4    = N_TOT * D / 4;

constexpr int KC           = 32;                // K per pipeline chunk
constexpr int CH_TOT       = NPAD / KC;         // 2216
constexpr int KSPLITS      = 74;                // GEMM1 split-K (grid 296)
constexpr int CH_PER_SPLIT = (CH_TOT + KSPLITS - 1) / KSPLITS;  // 30

// stage slot: AF(fp32 A) 16K | Ah 8K | Al 8K | Bh 4K | Bl 4K = 40 KB; 2 slots
constexpr int A_OFF_H = 16384;
constexpr int A_OFF_L = 24576;
constexpr int B_OFF_H = 32768;
constexpr int B_OFF_L = 36864;
constexpr int STAGE   = 40960;
constexpr int GEMM_SMEM = 2 * STAGE + 1024;

// ---------------- scratch (static device globals; no allocation) -------------
__device__ __align__(128) float          g_acc[N_TOT * D];
__device__ __align__(128) unsigned short g_eh[(size_t)NPAD * D];   // ego hi [n][64]
__device__ __align__(128) unsigned short g_el[(size_t)NPAD * D];   // ego lo
__device__ __align__(128) unsigned short g_wh[D * F];              // W^T hi [64][512]
__device__ __align__(128) unsigned short g_wl[D * F];              // W^T lo
__device__ __align__(128) float          g_p1[KSPLITS * 4 * 128 * D];

// ---------------- helpers ----------------
__device__ __forceinline__ uint32_t smem_u32(const void* p) {
    uint32_t a;
    asm("{ .reg .u64 t; cvta.to.shared.u64 t, %1; cvt.u32.u64 %0, t; }"
        : "=r"(a) : "l"(p));
    return a;
}
__device__ __forceinline__ uint32_t swz(uint32_t o) { return o ^ ((o >> 3) & 0x70); }

__device__ __forceinline__ void cp16(uint32_t dst, const void* src) {
    asm volatile("cp.async.cg.shared.global [%0], [%1], 16;"
                 :: "r"(dst), "l"(src) : "memory");
}
// zero-fill variant: copies sz bytes (0 or 16), zero-fills the rest
__device__ __forceinline__ void cp16z(uint32_t dst, const void* src, bool ok) {
    int sz = ok ? 16 : 0;
    asm volatile("cp.async.cg.shared.global [%0], [%1], 16, %2;"
                 :: "r"(dst), "l"(src), "r"(sz) : "memory");
}
__device__ __forceinline__ void cp_commit() {
    asm volatile("cp.async.commit_group;" ::: "memory");
}
template <int N>
__device__ __forceinline__ void cp_wait() {
    asm volatile("cp.async.wait_group %0;" :: "n"(N) : "memory");
}

// split 4 floats -> 4 bf16 hi (8B) + 4 bf16 lo (8B)
__device__ __forceinline__ void split4(const float4& x, uint2& hi, uint2& lo) {
    float v[4] = {x.x, x.y, x.z, x.w};
    unsigned int hw[2], lw[2];
#pragma unroll
    for (int p = 0; p < 2; p++) {
        __nv_bfloat16 h0 = __float2bfloat16(v[2 * p]);
        __nv_bfloat16 h1 = __float2bfloat16(v[2 * p + 1]);
        float r0 = v[2 * p]     - __bfloat162float(h0);
        float r1 = v[2 * p + 1] - __bfloat162float(h1);
        hw[p] = (unsigned)__bfloat16_as_ushort(h0) |
                ((unsigned)__bfloat16_as_ushort(h1) << 16);
        lw[p] = (unsigned)__bfloat16_as_ushort(__float2bfloat16(r0)) |
                ((unsigned)__bfloat16_as_ushort(__float2bfloat16(r1)) << 16);
    }
    hi = make_uint2(hw[0], hw[1]);
    lo = make_uint2(lw[0], lw[1]);
}

__device__ __forceinline__ void ldsm_x4(uint32_t* r, uint32_t a) {
    asm volatile("ldmatrix.sync.aligned.m8n8.x4.shared.b16 {%0,%1,%2,%3}, [%4];"
                 : "=r"(r[0]), "=r"(r[1]), "=r"(r[2]), "=r"(r[3]) : "r"(a));
}
__device__ __forceinline__ void ldsm_x4_t(uint32_t* r, uint32_t a) {
    asm volatile("ldmatrix.sync.aligned.m8n8.x4.trans.shared.b16 {%0,%1,%2,%3}, [%4];"
                 : "=r"(r[0]), "=r"(r[1]), "=r"(r[2]), "=r"(r[3]) : "r"(a));
}
__device__ __forceinline__ void mma_bf16(float* c, const uint32_t* a,
                                         uint32_t b0, uint32_t b1) {
    asm volatile(
        "mma.sync.aligned.m16n8k16.row.col.f32.bf16.bf16.f32 "
        "{%0,%1,%2,%3}, {%4,%5,%6,%7}, {%8,%9}, {%0,%1,%2,%3};"
        : "+f"(c[0]), "+f"(c[1]), "+f"(c[2]), "+f"(c[3])
        : "r"(a[0]), "r"(a[1]), "r"(a[2]), "r"(a[3]), "r"(b0), "r"(b1));
}

// ---------------- K0: acc = concat(user,item); ego hi/lo split ---------------
__global__ void k_init(const float* __restrict__ u, const float* __restrict__ it) {
    int i = blockIdx.x * blockDim.x + threadIdx.x;
    if (i < (NPAD - N_TOT) * D / 4) {
        uint2 z = make_uint2(0u, 0u);
        *(uint2*)(g_eh + (size_t)N_TOT * D + i * 4) = z;
        *(uint2*)(g_el + (size_t)N_TOT * D + i * 4) = z;
    }
    if (i >= NTOT4) return;
    int e = i << 2;
    float4 t;
    if (e < NU_ELEMS) t = *(const float4*)(u + e);
    else              t = *(const float4*)(it + (e - NU_ELEMS));
    *(float4*)(g_acc + e) = t;
    uint2 hi, lo;
    split4(t, hi, lo);
    *(uint2*)(g_eh + e) = hi;
    *(uint2*)(g_el + e) = lo;
}

// ---------------- reduce partials, fold filters, split W^T ----------------
__global__ void k_reduce1(const float* __restrict__ filt) {
    int gid = blockIdx.x * blockDim.x + threadIdx.x;  // 0..131071
    int out = gid >> 2, sub = gid & 3;
    int f = out >> 6, d = out & 63;
    int mt = f >> 7, fl = f & 127;
    float s = 0.f;
#pragma unroll 4
    for (int ks = sub; ks < KSPLITS; ks += 4)
        s += g_p1[((ks << 2) + mt) * 8192 + fl * 64 + d];
    s += __shfl_down_sync(0xffffffffu, s, 1);
    s += __shfl_down_sync(0xffffffffu, s, 2);
    if (sub == 0) {
        s *= filt[f];
        __nv_bfloat16 h = __float2bfloat16(s);
        float r = s - __bfloat162float(h);
        g_wh[d * F + f] = __bfloat16_as_ushort(h);
        g_wl[d * F + f] = __bfloat16_as_ushort(__float2bfloat16(r));
    }
}

// ---------------- pipelined warp-MMA GEMM ----------------
// C[128 x 64] = A[128 x K] * B[64 x K]^T, hi/lo bf16 split (3 MMA terms)
// A comes in as fp32 V via cp.async, converted smem->smem to hi/lo bf16.
// MODE 0 (proj = V^T ego):  A slice [KC n][128 f], B = ego hi/lo [KC n][64 d]
// MODE 1 (ego' = V W):      A rows  [128 m][KC f], B = W^T hi/lo [64 d][KC f]
template <int MODE>
__global__ __launch_bounds__(256, 2) void k_gemm(const float* __restrict__ vsrc) {
    extern __shared__ char smraw[];
    const uint32_t smb = smem_u32(smraw);
    const uint32_t sm0 = (smb + 1023) & ~1023u;
    char* smp = smraw + (sm0 - smb);

    const int tid  = threadIdx.x;
    const int w    = tid >> 5;
    const int lane = tid & 31;

    int m0, c0, nc;
    if (MODE == 0) {
        int mt = blockIdx.x & 3;
        int ks = blockIdx.x >> 2;
        m0 = mt * 128;                         // f-tile origin
        c0 = ks * CH_PER_SPLIT;
        nc = min(CH_PER_SPLIT, CH_TOT - c0);
    } else {
        m0 = blockIdx.x * 128;                 // n-tile origin
        c0 = 0;
        nc = F / KC;                           // 16
    }

    float acc[8][4];
#pragma unroll
    for (int nt = 0; nt < 8; nt++)
#pragma unroll
        for (int j = 0; j < 4; j++) acc[nt][j] = 0.f;

    // ---- cp.async stage: fp32 A chunk + bf16 B pair into slot ch&1 ----
    auto stage = [&](int ch) {
        const int k0 = (c0 + ch) * KC;
        const uint32_t sbuf = sm0 + (uint32_t)(ch & 1) * STAGE;
        // A fp32: 16 KB, linear, 4 cp16/thread
#pragma unroll
        for (int r = 0; r < 4; r++) {
            int j = tid + r * 256;
            const float* src;
            bool ok;
            if (MODE == 0) {
                int n = j >> 5, c = (j & 31) * 4;
                int gn = k0 + n;
                ok  = gn < N_TOT;
                src = vsrc + (size_t)(ok ? gn : 0) * F + m0 + c;
            } else {
                int m = j >> 3, c = (j & 7) * 4;
                int gm = m0 + m;
                ok  = gm < N_TOT;
                src = vsrc + (size_t)(ok ? gm : 0) * F + k0 + c;
            }
            cp16z(sbuf + j * 16, src, ok);
        }
        // B bf16 pair: 1 job/thread
        if (MODE == 0) {
            int n = tid >> 3, q = tid & 7;
            size_t src = (size_t)(k0 + n) * D + q * 8;
            uint32_t d = swz(n * 128 + q * 16);
            cp16(sbuf + B_OFF_H + d, g_eh + src);
            cp16(sbuf + B_OFF_L + d, g_el + src);
        } else {
            int dd = tid >> 2, q = tid & 3;
            size_t src = (size_t)dd * F + k0 + q * 8;
            uint32_t d = swz(dd * 64 + q * 16);
            cp16(sbuf + B_OFF_H + d, g_wh + src);
            cp16(sbuf + B_OFF_L + d, g_wl + src);
        }
        cp_commit();
    };

    // ---- convert fp32 A (smem) -> hi/lo bf16 (smem), 4 jobs/thread ----
    auto convertA = [&](int ch) {
        char* sb = smp + (ch & 1) * STAGE;
        const float4* af = (const float4*)sb;
#pragma unroll
        for (int r = 0; r < 4; r++) {
            int j = tid + r * 256;
            float4 x = af[j];
            uint2 hi, lo;
            split4(x, hi, lo);
            uint32_t d;
            if (MODE == 0) {
                int n = j >> 5, c = (j & 31) * 4;
                d = (uint32_t)(c >> 6) * 4096 + swz(n * 128 + (c & 63) * 2);
            } else {
                int m = j >> 3, c = (j & 7) * 4;
                d = swz(m * 64 + c * 2);
            }
            *(uint2*)(sb + A_OFF_H + d) = hi;
            *(uint2*)(sb + A_OFF_L + d) = lo;
        }
    };

    // fragment addressing
    const int a_k   = (lane & 7) | ((lane & 16) >> 1);        // MODE 0 (trans A)
    const uint32_t a_seg = (uint32_t)(w >> 2) * 4096;
    const uint32_t a_f2  = (uint32_t)((w * 16 + (lane & 8)) & 63) * 2;
    const int bt_k  = lane & 15;                              // MODE 0 (trans B)
    const int bt_n8 = ((lane >> 4) & 1) * 8;
    const int a_row  = w * 16 + (lane & 15);                  // MODE 1 (plain A)
    const int a_colh = (lane >> 4) * 8;
    const int bp_row = lane & 15;                             // MODE 1 (plain B)
    const int bp_k8  = ((lane >> 4) & 1) * 8;

    auto compute = [&](int ch) {
        const uint32_t buf = sm0 + (uint32_t)(ch & 1) * STAGE;
        const uint32_t sAh = buf + A_OFF_H, sAl = buf + A_OFF_L;
        const uint32_t sBh = buf + B_OFF_H, sBl = buf + B_OFF_L;
#pragma unroll
        for (int ks = 0; ks < KC / 16; ks++) {
            uint32_t ah[4], al[4];
            if (MODE == 0) {
                uint32_t ao = a_seg + swz((uint32_t)((ks * 16 + a_k) * 128) + a_f2);
                ldsm_x4_t(ah, sAh + ao);
                ldsm_x4_t(al, sAl + ao);
            } else {
                uint32_t ao = swz((uint32_t)(a_row * 64 + (ks * 16 + a_colh) * 2));
                ldsm_x4(ah, sAh + ao);
                ldsm_x4(al, sAl + ao);
            }
#pragma unroll
            for (int nt2 = 0; nt2 < 4; nt2++) {
                uint32_t bh[4], bl[4];
                if (MODE == 0) {
                    uint32_t bo = swz((uint32_t)((ks * 16 + bt_k) * 128 +
                                                 (nt2 * 16 + bt_n8) * 2));
                    ldsm_x4_t(bh, sBh + bo);
                    ldsm_x4_t(bl, sBl + bo);
                    float* cE = acc[2 * nt2];
                    float* cO = acc[2 * nt2 + 1];
                    mma_bf16(cE, ah, bh[0], bh[1]);
                    mma_bf16(cE, ah, bl[0], bl[1]);
                    mma_bf16(cE, al, bh[0], bh[1]);
                    mma_bf16(cO, ah, bh[2], bh[3]);
                    mma_bf16(cO, ah, bl[2], bl[3]);
                    mma_bf16(cO, al, bh[2], bh[3]);
                } else {
                    uint32_t bo = swz((uint32_t)((nt2 * 16 + bp_row) * 64 +
                                                 (ks * 16 + bp_k8) * 2));
                    ldsm_x4(bh, sBh + bo);
                    ldsm_x4(bl, sBl + bo);
                    float* cE = acc[2 * nt2];
                    float* cO = acc[2 * nt2 + 1];
                    mma_bf16(cE, ah, bh[0], bh[2]);
                    mma_bf16(cE, ah, bl[0], bl[2]);
                    mma_bf16(cE, al, bh[0], bh[2]);
                    mma_bf16(cO, ah, bh[1], bh[3]);
                    mma_bf16(cO, ah, bl[1], bl[3]);
                    mma_bf16(cO, al, bh[1], bh[3]);
                }
            }
        }
    };

    // ---- pipeline: 2 slots, 1-chunk lookahead, convert stage in between ----
    stage(0);
    for (int ch = 0; ch < nc; ch++) {
        if (ch + 1 < nc) {
            stage(ch + 1);
            cp_wait<1>();
        } else {
            cp_wait<0>();
        }
        __syncthreads();       // slot ch (AF + B) ready
        convertA(ch);
        __syncthreads();       // Ah/Al of slot ch visible
        compute(ch);
        __syncthreads();       // slot ch free for stage(ch+2)
    }

    // ---- epilogue ----
    const int r0   = w * 16 + (lane >> 2);
    const int ncol = 2 * (lane & 3);
    if (MODE == 0) {
        float* out = g_p1 + (size_t)blockIdx.x * 8192;
#pragma unroll
        for (int nt = 0; nt < 8; nt++) {
            int n = nt * 8 + ncol;
            *(float2*)(out + r0 * 64 + n)       = make_float2(acc[nt][0], acc[nt][1]);
            *(float2*)(out + (r0 + 8) * 64 + n) = make_float2(acc[nt][2], acc[nt][3]);
        }
    } else {
#pragma unroll
        for (int half = 0; half < 2; half++) {
            int m = m0 + r0 + half * 8;
            if (m >= N_TOT) continue;
            float* ap = g_acc + (size_t)m * D;
            unsigned short* ehp = g_eh + (size_t)m * D;
            unsigned short* elp = g_el + (size_t)m * D;
#pragma unroll
            for (int nt = 0; nt < 8; nt++) {
                int n = nt * 8 + ncol;
                float cx = acc[nt][half * 2], cy = acc[nt][half * 2 + 1];
                float2 a = *(float2*)(ap + n);
                a.x += cx; a.y += cy;
                *(float2*)(ap + n) = a;
                __nv_bfloat16 hx = __float2bfloat16(cx);
                __nv_bfloat16 hy = __float2bfloat16(cy);
                float rx = cx - __bfloat162float(hx);
                float ry = cy - __bfloat162float(hy);
                unsigned int hw = (unsigned)__bfloat16_as_ushort(hx) |
                                  ((unsigned)__bfloat16_as_ushort(hy) << 16);
                unsigned int lw = (unsigned)__bfloat16_as_ushort(__float2bfloat16(rx)) |
                                  ((unsigned)__bfloat16_as_ushort(__float2bfloat16(ry)) << 16);
                *(unsigned int*)(ehp + n) = hw;
                *(unsigned int*)(elp + n) = lw;
            }
        }
    }
}

// ---------------- K4: out = acc / (L+1) ----------------
__global__ void k_final(float* __restrict__ out) {
    int i = blockIdx.x * blockDim.x + threadIdx.x;
    if (i >= NTOT4) return;
    int e = i << 2;
    float4 t = *(const float4*)(g_acc + e);
    t.x *= 0.25f; t.y *= 0.25f; t.z *= 0.25f; t.w *= 0.25f;
    *(float4*)(out + e) = t;
}

// ---------------- launcher ----------------
extern "C" void kernel_launch(void* const* d_in, const int* in_sizes, int n_in,
                              void* d_out, int out_size) {
    const float* user    = (const float*)d_in[0];
    const float* item    = (const float*)d_in[1];
    const float* v       = (const float*)d_in[2];
    const float* filters = (const float*)d_in[3];
    float* out = (float*)d_out;

    cudaFuncSetAttribute(k_gemm<0>, cudaFuncAttributeMaxDynamicSharedMemorySize, GEMM_SMEM);
    cudaFuncSetAttribute(k_gemm<1>, cudaFuncAttributeMaxDynamicSharedMemorySize, GEMM_SMEM);

    const int ew_blocks = (NTOT4 + 255) / 256;
    k_init<<<ew_blocks, 256>>>(user, item);

    for (int l = 0; l < N_LAYERS; l++) {
        k_gemm<0><<<KSPLITS * 4, 256, GEMM_SMEM>>>(v);       // proj partials
        k_reduce1<<<512, 256>>>(filters + l * F);            // W^T hi/lo
        k_gemm<1><<<NPAD / 128, 256, GEMM_SMEM>>>(v);        // ego' = V W ; acc+=, split
    }

    k_final<<<ew_blocks, 256>>>(out);
}